// round 11
// baseline (speedup 1.0000x reference)
#include <cuda_runtime.h>

// QuantumConvolution: B=32, Cin=8, Cout=16, H=W=32, K=3, NQ=3, DRC=3, IT=30.
// R11 (= R10 resubmit; R10 hit an infra failure, kernel never ran):
//   single-wave packing (NBAND=3 -> grid 1536 < 1776 slots @ 12 blocks/SM),
//   incremental (il,j) index (no div/mod), per-layer batched __sincosf,
//   gate constants precomputed once in a tiny kernel, measurement fold.
//   Removed the #pragma unroll on the variable-trip smem fill loop.

#define BB    32
#define CIN   8
#define COUT  16
#define HW    32
#define ITDIM 30
#define NBAND 3
#define BROWS 10                // output rows per band (3 x 10 = 30, exact)
#define NTHREADS 64
#define ROWS_MAX 12             // input rows held (BROWS + 2)
#define ROW_STRIDE 33
#define CH_STRIDE (ROWS_MAX * ROW_STRIDE)   // 396
#define NGATE (COUT * CIN * 9)  // 1152

__device__ float4 g_gc[NGATE];  // Rot row0: (u00r, u00i, u01r, u01i)
__device__ float  g_pm[NGATE];  // 0.5 * input_params

__global__ void precompute_kernel(const float* __restrict__ input_params,
                                  const float* __restrict__ weights)
{
    int e = blockIdx.x * blockDim.x + threadIdx.x;
    if (e >= NGATE) return;
    g_pm[e] = 0.5f * input_params[e];
    const float* w = weights + (size_t)e * 3;
    float phi = w[0], th = w[1], om = w[2];
    float st, ct;  sincosf(0.5f * th, &st, &ct);
    float sa, ca;  sincosf(0.5f * (phi + om), &sa, &ca);
    float sb, cb;  sincosf(0.5f * (phi - om), &sb, &cb);
    // u00 = ( ca*ct, -sa*ct),  u01 = (-cb*st, -sb*st)
    g_gc[e] = make_float4(ca * ct, -sa * ct, -cb * st, -sb * st);
}

__global__ __launch_bounds__(NTHREADS, 12)
void qconv_kernel(const float* __restrict__ inputs,   // [32][8][32][32]
                  float* __restrict__ out)            // [32][16][30][30]
{
    __shared__ float  s_in[CIN * CH_STRIDE];
    __shared__ float  s_pm[CIN * 9];
    __shared__ float4 s_gc[CIN * 9];

    const int cout = blockIdx.x;
    const int b    = blockIdx.y;
    const int z    = blockIdx.z;
    const int tid  = threadIdx.x;
    const int cin  = tid & 7;
    const int grp  = tid >> 3;          // 8 position groups

    const int row0 = z * BROWS;

    // ---- Load band patch (float4, coalesced) into padded smem ----
    const float4* inb4 = (const float4*)inputs + (size_t)b * (CIN * HW * HW / 4);
    #pragma unroll 1
    for (int c = 0; c < CIN; c++) {
        for (int t4 = tid; t4 < ROWS_MAX * 8; t4 += NTHREADS) {
            int r    = t4 >> 3;
            int col4 = t4 & 7;
            float4 v = inb4[(c * HW + row0 + r) * 8 + col4];
            float* dst = &s_in[c * CH_STRIDE + r * ROW_STRIDE + col4 * 4];
            dst[0] = v.x; dst[1] = v.y; dst[2] = v.z; dst[3] = v.w;
        }
    }

    // ---- Copy precomputed gate constants (L2-resident) ----
    {
        const int base = cout * CIN * 9;
        for (int e = tid; e < CIN * 9; e += NTHREADS) {
            s_gc[e] = g_gc[base + e];
            s_pm[e] = g_pm[base + e];
        }
    }
    __syncthreads();

    const float*  chan = &s_in[cin * CH_STRIDE];
    const float*  pmc  = &s_pm[cin * 9];
    const float4* gcc  = &s_gc[cin * 9];

    // Apply SU(2) gate V = [[a, -t],[conj(t), conj(a)]] on pairs with stride ST
    #define APPLY(AR, AI, TR, TI, ST)                                           \
    {                                                                           \
        _Pragma("unroll")                                                       \
        for (int a0 = 0; a0 < 8; a0++) {                                        \
            if ((a0 & (ST)) == 0) {                                             \
                int p = a0 | (ST);                                              \
                float x0r = sr[a0], x0i = si[a0];                               \
                float x1r = sr[p],  x1i = si[p];                                \
                sr[a0] = (AR) * x0r - (AI) * x0i - (TR) * x1r + (TI) * x1i;     \
                si[a0] = (AR) * x0i + (AI) * x0r - (TR) * x1i - (TI) * x1r;     \
                sr[p]  = (TR) * x0r + (TI) * x0i + (AR) * x1r + (AI) * x1i;     \
                si[p]  = (TR) * x0i - (TI) * x0r + (AR) * x1i - (AI) * x1r;     \
            }                                                                   \
        }                                                                       \
    }

    // Fused (Rot * RY) with PREcomputed sincos: a = u00*c+u01*s, t = u00*s-u01*c
    #define FUSED_GATE_PRE(G, SN, CS, ST)                                       \
    {                                                                           \
        float4 u = gcc[(G)];                                                    \
        float ar = u.x * (CS) + u.z * (SN);                                     \
        float ai = u.y * (CS) + u.w * (SN);                                     \
        float tr = u.x * (SN) - u.z * (CS);                                     \
        float ti = u.y * (SN) - u.w * (CS);                                     \
        APPLY(ar, ai, tr, ti, ST)                                               \
    }

    #define CNOT_RING()                                                             \
    {                                                                               \
        float t;                                                                    \
        t = sr[4]; sr[4] = sr[6]; sr[6] = t;  t = si[4]; si[4] = si[6]; si[6] = t;  \
        t = sr[5]; sr[5] = sr[7]; sr[7] = t;  t = si[5]; si[5] = si[7]; si[7] = t;  \
        t = sr[2]; sr[2] = sr[3]; sr[3] = t;  t = si[2]; si[2] = si[3]; si[3] = t;  \
        t = sr[6]; sr[6] = sr[7]; sr[7] = t;  t = si[6]; si[6] = si[7]; si[7] = t;  \
        t = sr[1]; sr[1] = sr[5]; sr[5] = t;  t = si[1]; si[1] = si[5]; si[5] = t;  \
        t = sr[3]; sr[3] = sr[7]; sr[7] = t;  t = si[3]; si[3] = si[7]; si[7] = t;  \
    }

    const int npos = BROWS * ITDIM;     // 300

    int il = 0, j = grp;                // incremental (row, col); grp < 30
    #pragma unroll 1
    for (int k = grp; k < npos; k += 8) {
        const float* win = chan + il * ROW_STRIDE + j;

        float sr[8], si[8];

        // ======== Layer 0: Kronecker product of fused (Rot*RY)|0> columns ========
        {
            float sn, cs;
            __sincosf(win[0] * pmc[0], &sn, &cs);
            float4 u = gcc[0];
            float a0r = u.x * cs + u.z * sn,  a0i = u.y * cs + u.w * sn;
            float b0r = u.x * sn - u.z * cs,  b0i = u.w * cs - u.y * sn;  // conj(t0)
            __sincosf(win[1] * pmc[1], &sn, &cs);
            u = gcc[1];
            float a1r = u.x * cs + u.z * sn,  a1i = u.y * cs + u.w * sn;
            float b1r = u.x * sn - u.z * cs,  b1i = u.w * cs - u.y * sn;
            __sincosf(win[2] * pmc[2], &sn, &cs);
            u = gcc[2];
            float a2r = u.x * cs + u.z * sn,  a2i = u.y * cs + u.w * sn;
            float b2r = u.x * sn - u.z * cs,  b2i = u.w * cs - u.y * sn;

            float m0r = a1r * a2r - a1i * a2i,  m0i = a1r * a2i + a1i * a2r;
            float m1r = a1r * b2r - a1i * b2i,  m1i = a1r * b2i + a1i * b2r;
            float m2r = b1r * a2r - b1i * a2i,  m2i = b1r * a2i + b1i * a2r;
            float m3r = b1r * b2r - b1i * b2i,  m3i = b1r * b2i + b1i * b2r;

            sr[0] = a0r * m0r - a0i * m0i;  si[0] = a0r * m0i + a0i * m0r;
            sr[1] = a0r * m1r - a0i * m1i;  si[1] = a0r * m1i + a0i * m1r;
            sr[2] = a0r * m2r - a0i * m2i;  si[2] = a0r * m2i + a0i * m2r;
            sr[3] = a0r * m3r - a0i * m3i;  si[3] = a0r * m3i + a0i * m3r;
            sr[4] = b0r * m0r - b0i * m0i;  si[4] = b0r * m0i + b0i * m0r;
            sr[5] = b0r * m1r - b0i * m1i;  si[5] = b0r * m1i + b0i * m1r;
            sr[6] = b0r * m2r - b0i * m2i;  si[6] = b0r * m2i + b0i * m2r;
            sr[7] = b0r * m3r - b0i * m3i;  si[7] = b0r * m3i + b0i * m3r;
        }
        CNOT_RING()

        // ======== Layer 1 (sincos batched before state updates) ========
        {
            float sn3, cs3, sn4, cs4, sn5, cs5;
            __sincosf(win[ROW_STRIDE + 0] * pmc[3], &sn3, &cs3);
            __sincosf(win[ROW_STRIDE + 1] * pmc[4], &sn4, &cs4);
            __sincosf(win[ROW_STRIDE + 2] * pmc[5], &sn5, &cs5);
            FUSED_GATE_PRE(3, sn3, cs3, 4)
            FUSED_GATE_PRE(4, sn4, cs4, 2)
            FUSED_GATE_PRE(5, sn5, cs5, 1)
        }
        CNOT_RING()

        // ======== Layer 2: wires 0,1 applied; wire-2 gate + ring + <Z2> folded:
        //          Ring' Z2 Ring = Z0 Z1 Z2 -> Z0 (x) Z1 (x) (V2' Z V2) ========
        float acc;
        {
            float sn6, cs6, sn7, cs7, sn8, cs8;
            __sincosf(win[2 * ROW_STRIDE + 0] * pmc[6], &sn6, &cs6);
            __sincosf(win[2 * ROW_STRIDE + 1] * pmc[7], &sn7, &cs7);
            __sincosf(win[2 * ROW_STRIDE + 2] * pmc[8], &sn8, &cs8);
            FUSED_GATE_PRE(6, sn6, cs6, 4)
            FUSED_GATE_PRE(7, sn7, cs7, 2)

            float4 u = gcc[8];
            float ar = u.x * cs8 + u.z * sn8;
            float ai = u.y * cs8 + u.w * sn8;
            float tr = u.x * sn8 - u.z * cs8;
            float ti = u.y * sn8 - u.w * cs8;
            // M = [[m, p],[conj(p), -m]], m = |a|^2-|t|^2, p = -2*conj(a)*t.
            // <x|M|x> = m(|x0|^2-|x1|^2) + 2*Re(p conj(x0) x1) -> fold 2 into p.
            float m  = ar * ar + ai * ai - tr * tr - ti * ti;
            float pr = -4.0f * (ar * tr + ai * ti);
            float pi = -4.0f * (ar * ti - ai * tr);

            #define PAIR_E(K)                                                   \
                (m  * (sr[2*(K)] * sr[2*(K)] + si[2*(K)] * si[2*(K)]            \
                     - sr[2*(K)+1] * sr[2*(K)+1] - si[2*(K)+1] * si[2*(K)+1])   \
               + pr * (sr[2*(K)] * sr[2*(K)+1] + si[2*(K)] * si[2*(K)+1])       \
               - pi * (sr[2*(K)] * si[2*(K)+1] - si[2*(K)] * sr[2*(K)+1]))
            acc = PAIR_E(0) - PAIR_E(1) - PAIR_E(2) + PAIR_E(3);
            #undef PAIR_E
        }

        // reduce over the 8 cin lanes
        acc += __shfl_xor_sync(0xFFFFFFFFu, acc, 1);
        acc += __shfl_xor_sync(0xFFFFFFFFu, acc, 2);
        acc += __shfl_xor_sync(0xFFFFFFFFu, acc, 4);
        if (cin == 0)
            out[((size_t)b * COUT + cout) * (ITDIM * ITDIM) + (row0 + il) * ITDIM + j] = acc;

        // incremental index update (no div/mod)
        j += 8;
        if (j >= ITDIM) { j -= ITDIM; il++; }
    }

    #undef APPLY
    #undef FUSED_GATE_PRE
    #undef CNOT_RING
}

extern "C" void kernel_launch(void* const* d_in, const int* in_sizes, int n_in,
                              void* d_out, int out_size)
{
    const float* inputs       = (const float*)d_in[0];
    const float* input_params = (const float*)d_in[1];
    const float* weights      = (const float*)d_in[2];
    float* out = (float*)d_out;

    precompute_kernel<<<(NGATE + 127) / 128, 128>>>(input_params, weights);
    dim3 grid(COUT, BB, NBAND);   // (cout, b, row band) = 16 x 32 x 3 = 1536 blocks
    qconv_kernel<<<grid, NTHREADS>>>(inputs, out);
}

// round 14
// speedup vs baseline: 1.1429x; 1.1429x over previous
#include <cuda_runtime.h>

// QuantumConvolution: B=32, Cin=8, Cout=16, H=W=32, K=3, NQ=3, DRC=3, IT=30.
// R12: resident-warp maximization (the variable that tracks perf across R8/R9/R11):
//   128-thread blocks (16 pos-groups x 8 cin), launch_bounds(128,8) -> 64 regs,
//   32-warp/SM ceiling; NBAND=2 (15-row bands) -> grid 1024 <= 1184 slots,
//   single wave at ~7 blocks/SM. Body = R11's lean version (batched sincos,
//   div-free index, precomputed gate constants, measurement fold).

#define BB    32
#define CIN   8
#define COUT  16
#define HW    32
#define ITDIM 30
#define NBAND 2
#define BROWS 15                // output rows per band (2 x 15 = 30, exact)
#define NTHREADS 128
#define NGRP  16                // position groups (tid >> 3)
#define ROWS_MAX 17             // input rows held (BROWS + 2)
#define ROW_STRIDE 33
#define CH_STRIDE 564           // >= 17*33=561, = 4 mod 8 -> 8 cin bases on distinct bank quads
#define NGATE (COUT * CIN * 9)  // 1152

__device__ float4 g_gc[NGATE];  // Rot row0: (u00r, u00i, u01r, u01i)
__device__ float  g_pm[NGATE];  // 0.5 * input_params

__global__ void precompute_kernel(const float* __restrict__ input_params,
                                  const float* __restrict__ weights)
{
    int e = blockIdx.x * blockDim.x + threadIdx.x;
    if (e >= NGATE) return;
    g_pm[e] = 0.5f * input_params[e];
    const float* w = weights + (size_t)e * 3;
    float phi = w[0], th = w[1], om = w[2];
    float st, ct;  sincosf(0.5f * th, &st, &ct);
    float sa, ca;  sincosf(0.5f * (phi + om), &sa, &ca);
    float sb, cb;  sincosf(0.5f * (phi - om), &sb, &cb);
    // u00 = ( ca*ct, -sa*ct),  u01 = (-cb*st, -sb*st)
    g_gc[e] = make_float4(ca * ct, -sa * ct, -cb * st, -sb * st);
}

__global__ __launch_bounds__(NTHREADS, 8)
void qconv_kernel(const float* __restrict__ inputs,   // [32][8][32][32]
                  float* __restrict__ out)            // [32][16][30][30]
{
    __shared__ float  s_in[CIN * CH_STRIDE];
    __shared__ float  s_pm[CIN * 9];
    __shared__ float4 s_gc[CIN * 9];

    const int cout = blockIdx.x;
    const int b    = blockIdx.y;
    const int z    = blockIdx.z;
    const int tid  = threadIdx.x;
    const int cin  = tid & 7;
    const int grp  = tid >> 3;          // 16 position groups

    const int row0 = z * BROWS;

    // ---- Load band patch (float4, coalesced) into padded smem ----
    const float4* inb4 = (const float4*)inputs + (size_t)b * (CIN * HW * HW / 4);
    #pragma unroll 1
    for (int c = 0; c < CIN; c++) {
        for (int t4 = tid; t4 < ROWS_MAX * 8; t4 += NTHREADS) {
            int r    = t4 >> 3;
            int col4 = t4 & 7;
            float4 v = inb4[(c * HW + row0 + r) * 8 + col4];
            float* dst = &s_in[c * CH_STRIDE + r * ROW_STRIDE + col4 * 4];
            dst[0] = v.x; dst[1] = v.y; dst[2] = v.z; dst[3] = v.w;
        }
    }

    // ---- Copy precomputed gate constants (L2-resident) ----
    {
        const int base = cout * CIN * 9;
        for (int e = tid; e < CIN * 9; e += NTHREADS) {
            s_gc[e] = g_gc[base + e];
            s_pm[e] = g_pm[base + e];
        }
    }
    __syncthreads();

    const float*  chan = &s_in[cin * CH_STRIDE];
    const float*  pmc  = &s_pm[cin * 9];
    const float4* gcc  = &s_gc[cin * 9];

    // Apply SU(2) gate V = [[a, -t],[conj(t), conj(a)]] on pairs with stride ST
    #define APPLY(AR, AI, TR, TI, ST)                                           \
    {                                                                           \
        _Pragma("unroll")                                                       \
        for (int a0 = 0; a0 < 8; a0++) {                                        \
            if ((a0 & (ST)) == 0) {                                             \
                int p = a0 | (ST);                                              \
                float x0r = sr[a0], x0i = si[a0];                               \
                float x1r = sr[p],  x1i = si[p];                                \
                sr[a0] = (AR) * x0r - (AI) * x0i - (TR) * x1r + (TI) * x1i;     \
                si[a0] = (AR) * x0i + (AI) * x0r - (TR) * x1i - (TI) * x1r;     \
                sr[p]  = (TR) * x0r + (TI) * x0i + (AR) * x1r + (AI) * x1i;     \
                si[p]  = (TR) * x0i - (TI) * x0r + (AR) * x1i - (AI) * x1r;     \
            }                                                                   \
        }                                                                       \
    }

    // Fused (Rot * RY) with PREcomputed sincos: a = u00*c+u01*s, t = u00*s-u01*c
    #define FUSED_GATE_PRE(G, SN, CS, ST)                                       \
    {                                                                           \
        float4 u = gcc[(G)];                                                    \
        float ar = u.x * (CS) + u.z * (SN);                                     \
        float ai = u.y * (CS) + u.w * (SN);                                     \
        float tr = u.x * (SN) - u.z * (CS);                                     \
        float ti = u.y * (SN) - u.w * (CS);                                     \
        APPLY(ar, ai, tr, ti, ST)                                               \
    }

    #define CNOT_RING()                                                             \
    {                                                                               \
        float t;                                                                    \
        t = sr[4]; sr[4] = sr[6]; sr[6] = t;  t = si[4]; si[4] = si[6]; si[6] = t;  \
        t = sr[5]; sr[5] = sr[7]; sr[7] = t;  t = si[5]; si[5] = si[7]; si[7] = t;  \
        t = sr[2]; sr[2] = sr[3]; sr[3] = t;  t = si[2]; si[2] = si[3]; si[3] = t;  \
        t = sr[6]; sr[6] = sr[7]; sr[7] = t;  t = si[6]; si[6] = si[7]; si[7] = t;  \
        t = sr[1]; sr[1] = sr[5]; sr[5] = t;  t = si[1]; si[1] = si[5]; si[5] = t;  \
        t = sr[3]; sr[3] = sr[7]; sr[7] = t;  t = si[3]; si[3] = si[7]; si[7] = t;  \
    }

    const int npos = BROWS * ITDIM;     // 450

    int il = 0, j = grp;                // incremental (row, col)
    if (j >= ITDIM) { j -= ITDIM; }     // grp < 30, so j < 30 already; keep for safety
    #pragma unroll 1
    for (int k = grp; k < npos; k += NGRP) {
        const float* win = chan + il * ROW_STRIDE + j;

        float sr[8], si[8];

        // ======== Layer 0: Kronecker product of fused (Rot*RY)|0> columns ========
        {
            float sn, cs;
            __sincosf(win[0] * pmc[0], &sn, &cs);
            float4 u = gcc[0];
            float a0r = u.x * cs + u.z * sn,  a0i = u.y * cs + u.w * sn;
            float b0r = u.x * sn - u.z * cs,  b0i = u.w * cs - u.y * sn;  // conj(t0)
            __sincosf(win[1] * pmc[1], &sn, &cs);
            u = gcc[1];
            float a1r = u.x * cs + u.z * sn,  a1i = u.y * cs + u.w * sn;
            float b1r = u.x * sn - u.z * cs,  b1i = u.w * cs - u.y * sn;
            __sincosf(win[2] * pmc[2], &sn, &cs);
            u = gcc[2];
            float a2r = u.x * cs + u.z * sn,  a2i = u.y * cs + u.w * sn;
            float b2r = u.x * sn - u.z * cs,  b2i = u.w * cs - u.y * sn;

            float m0r = a1r * a2r - a1i * a2i,  m0i = a1r * a2i + a1i * a2r;
            float m1r = a1r * b2r - a1i * b2i,  m1i = a1r * b2i + a1i * b2r;
            float m2r = b1r * a2r - b1i * a2i,  m2i = b1r * a2i + b1i * a2r;
            float m3r = b1r * b2r - b1i * b2i,  m3i = b1r * b2i + b1i * b2r;

            sr[0] = a0r * m0r - a0i * m0i;  si[0] = a0r * m0i + a0i * m0r;
            sr[1] = a0r * m1r - a0i * m1i;  si[1] = a0r * m1i + a0i * m1r;
            sr[2] = a0r * m2r - a0i * m2i;  si[2] = a0r * m2i + a0i * m2r;
            sr[3] = a0r * m3r - a0i * m3i;  si[3] = a0r * m3i + a0i * m3r;
            sr[4] = b0r * m0r - b0i * m0i;  si[4] = b0r * m0i + b0i * m0r;
            sr[5] = b0r * m1r - b0i * m1i;  si[5] = b0r * m1i + b0i * m1r;
            sr[6] = b0r * m2r - b0i * m2i;  si[6] = b0r * m2i + b0i * m2r;
            sr[7] = b0r * m3r - b0i * m3i;  si[7] = b0r * m3i + b0i * m3r;
        }
        CNOT_RING()

        // ======== Layer 1 (sincos batched before state updates) ========
        {
            float sn3, cs3, sn4, cs4, sn5, cs5;
            __sincosf(win[ROW_STRIDE + 0] * pmc[3], &sn3, &cs3);
            __sincosf(win[ROW_STRIDE + 1] * pmc[4], &sn4, &cs4);
            __sincosf(win[ROW_STRIDE + 2] * pmc[5], &sn5, &cs5);
            FUSED_GATE_PRE(3, sn3, cs3, 4)
            FUSED_GATE_PRE(4, sn4, cs4, 2)
            FUSED_GATE_PRE(5, sn5, cs5, 1)
        }
        CNOT_RING()

        // ======== Layer 2: wires 0,1 applied; wire-2 gate + ring + <Z2> folded:
        //          Ring' Z2 Ring = Z0 Z1 Z2 -> Z0 (x) Z1 (x) (V2' Z V2) ========
        float acc;
        {
            float sn6, cs6, sn7, cs7, sn8, cs8;
            __sincosf(win[2 * ROW_STRIDE + 0] * pmc[6], &sn6, &cs6);
            __sincosf(win[2 * ROW_STRIDE + 1] * pmc[7], &sn7, &cs7);
            __sincosf(win[2 * ROW_STRIDE + 2] * pmc[8], &sn8, &cs8);
            FUSED_GATE_PRE(6, sn6, cs6, 4)
            FUSED_GATE_PRE(7, sn7, cs7, 2)

            float4 u = gcc[8];
            float ar = u.x * cs8 + u.z * sn8;
            float ai = u.y * cs8 + u.w * sn8;
            float tr = u.x * sn8 - u.z * cs8;
            float ti = u.y * sn8 - u.w * cs8;
            // M = [[m, p],[conj(p), -m]], m = |a|^2-|t|^2, p = -2*conj(a)*t.
            // <x|M|x> = m(|x0|^2-|x1|^2) + 2*Re(p conj(x0) x1) -> fold 2 into p.
            float m  = ar * ar + ai * ai - tr * tr - ti * ti;
            float pr = -4.0f * (ar * tr + ai * ti);
            float pi = -4.0f * (ar * ti - ai * tr);

            #define PAIR_E(K)                                                   \
                (m  * (sr[2*(K)] * sr[2*(K)] + si[2*(K)] * si[2*(K)]            \
                     - sr[2*(K)+1] * sr[2*(K)+1] - si[2*(K)+1] * si[2*(K)+1])   \
               + pr * (sr[2*(K)] * sr[2*(K)+1] + si[2*(K)] * si[2*(K)+1])       \
               - pi * (sr[2*(K)] * si[2*(K)+1] - si[2*(K)] * sr[2*(K)+1]))
            acc = PAIR_E(0) - PAIR_E(1) - PAIR_E(2) + PAIR_E(3);
            #undef PAIR_E
        }

        // reduce over the 8 cin lanes
        acc += __shfl_xor_sync(0xFFFFFFFFu, acc, 1);
        acc += __shfl_xor_sync(0xFFFFFFFFu, acc, 2);
        acc += __shfl_xor_sync(0xFFFFFFFFu, acc, 4);
        if (cin == 0)
            out[((size_t)b * COUT + cout) * (ITDIM * ITDIM) + (row0 + il) * ITDIM + j] = acc;

        // incremental index update (no div/mod); step NGRP=16 < ITDIM -> one wrap max
        j += NGRP;
        if (j >= ITDIM) { j -= ITDIM; il++; }
    }

    #undef APPLY
    #undef FUSED_GATE_PRE
    #undef CNOT_RING
}

extern "C" void kernel_launch(void* const* d_in, const int* in_sizes, int n_in,
                              void* d_out, int out_size)
{
    const float* inputs       = (const float*)d_in[0];
    const float* input_params = (const float*)d_in[1];
    const float* weights      = (const float*)d_in[2];
    float* out = (float*)d_out;

    precompute_kernel<<<(NGATE + 127) / 128, 128>>>(input_params, weights);
    dim3 grid(COUT, BB, NBAND);   // (cout, b, row band) = 16 x 32 x 2 = 1024 blocks
    qconv_kernel<<<grid, NTHREADS>>>(inputs, out);
}

// round 17
// speedup vs baseline: 1.2511x; 1.0947x over previous
#include <cuda_runtime.h>

// QuantumConvolution: B=32, Cin=8, Cout=16, H=W=32, K=3, NQ=3, DRC=3, IT=30.
// R17: ILP-2 (two independent circuits per thread: positions k and k+225,
//   sharing gate-constant loads), restructured in the macro style of the
//   known-good R14 artifact (R15/R16 = same logic via templates hit
//   back-to-back container failures; this removes that structural delta).
//   launch_bounds(128,5) -> 102-reg budget. 128-thread blocks (16 grp x 8 cin),
//   NBAND=2 (grid 1024). Layer-0 Kronecker collapse, fused Rot*RY SU(2) gates,
//   measurement fold, precomputed gate constants.

#define BB    32
#define CIN   8
#define COUT  16
#define HW    32
#define ITDIM 30
#define NBAND 2
#define BROWS 15
#define NTHREADS 128
#define NGRP  16
#define HALF  225               // npos/2 = 450/2
#define ROWS_MAX 17
#define ROW_STRIDE 33
#define CH_STRIDE 564
#define NGATE (COUT * CIN * 9)  // 1152

__device__ float4 g_gc[NGATE];  // Rot row0: (u00r, u00i, u01r, u01i)
__device__ float  g_pm[NGATE];  // 0.5 * input_params

__global__ void precompute_kernel(const float* __restrict__ input_params,
                                  const float* __restrict__ weights)
{
    int e = blockIdx.x * blockDim.x + threadIdx.x;
    if (e >= NGATE) return;
    g_pm[e] = 0.5f * input_params[e];
    const float* w = weights + (size_t)e * 3;
    float phi = w[0], th = w[1], om = w[2];
    float st, ct;  sincosf(0.5f * th, &st, &ct);
    float sa, ca;  sincosf(0.5f * (phi + om), &sa, &ca);
    float sb, cb;  sincosf(0.5f * (phi - om), &sb, &cb);
    // u00 = ( ca*ct, -sa*ct),  u01 = (-cb*st, -sb*st)
    g_gc[e] = make_float4(ca * ct, -sa * ct, -cb * st, -sb * st);
}

__global__ __launch_bounds__(NTHREADS, 5)
void qconv_kernel(const float* __restrict__ inputs,   // [32][8][32][32]
                  float* __restrict__ out)            // [32][16][30][30]
{
    __shared__ float  s_in[CIN * CH_STRIDE];
    __shared__ float  s_pm[CIN * 9];
    __shared__ float4 s_gc[CIN * 9];

    const int cout = blockIdx.x;
    const int b    = blockIdx.y;
    const int z    = blockIdx.z;
    const int tid  = threadIdx.x;
    const int cin  = tid & 7;
    const int grp  = tid >> 3;          // 16 position groups

    const int row0 = z * BROWS;

    // ---- Load band patch (float4, coalesced) into padded smem ----
    const float4* inb4 = (const float4*)inputs + (size_t)b * (CIN * HW * HW / 4);
    #pragma unroll 1
    for (int c = 0; c < CIN; c++) {
        for (int t4 = tid; t4 < ROWS_MAX * 8; t4 += NTHREADS) {
            int r    = t4 >> 3;
            int col4 = t4 & 7;
            float4 v = inb4[(c * HW + row0 + r) * 8 + col4];
            float* dst = &s_in[c * CH_STRIDE + r * ROW_STRIDE + col4 * 4];
            dst[0] = v.x; dst[1] = v.y; dst[2] = v.z; dst[3] = v.w;
        }
    }

    // ---- Copy precomputed gate constants (L2-resident) ----
    {
        const int base = cout * CIN * 9;
        for (int e = tid; e < CIN * 9; e += NTHREADS) {
            s_gc[e] = g_gc[base + e];
            s_pm[e] = g_pm[base + e];
        }
    }
    __syncthreads();

    const float*  chan = &s_in[cin * CH_STRIDE];
    const float*  pmc  = &s_pm[cin * 9];
    const float4* gcc  = &s_gc[cin * 9];

    float* outp = out + ((size_t)b * COUT + cout) * (ITDIM * ITDIM) + row0 * ITDIM;

    // Apply SU(2) gate V = [[a,-t],[conj(t),conj(a)]] (from u, sn, cs) to state
    // arrays SR/SI on pair stride ST.
    #define APPLY_FUSED(U, SN, CS, SR, SI, ST)                                  \
    {                                                                           \
        float ar = (U).x * (CS) + (U).z * (SN);                                 \
        float ai = (U).y * (CS) + (U).w * (SN);                                 \
        float tr = (U).x * (SN) - (U).z * (CS);                                 \
        float ti = (U).y * (SN) - (U).w * (CS);                                 \
        _Pragma("unroll")                                                       \
        for (int a0 = 0; a0 < 8; a0++) {                                        \
            if ((a0 & (ST)) == 0) {                                             \
                int p = a0 | (ST);                                              \
                float x0r = SR[a0], x0i = SI[a0];                               \
                float x1r = SR[p],  x1i = SI[p];                                \
                SR[a0] = ar * x0r - ai * x0i - tr * x1r + ti * x1i;             \
                SI[a0] = ar * x0i + ai * x0r - tr * x1i - ti * x1r;             \
                SR[p]  = tr * x0r + ti * x0i + ar * x1r + ai * x1i;             \
                SI[p]  = tr * x0i - ti * x0r + ar * x1i - ai * x1r;             \
            }                                                                   \
        }                                                                       \
    }

    #define CNOT_RING(SR, SI)                                                       \
    {                                                                               \
        float t;                                                                    \
        t = SR[4]; SR[4] = SR[6]; SR[6] = t;  t = SI[4]; SI[4] = SI[6]; SI[6] = t;  \
        t = SR[5]; SR[5] = SR[7]; SR[7] = t;  t = SI[5]; SI[5] = SI[7]; SI[7] = t;  \
        t = SR[2]; SR[2] = SR[3]; SR[3] = t;  t = SI[2]; SI[2] = SI[3]; SI[3] = t;  \
        t = SR[6]; SR[6] = SR[7]; SR[7] = t;  t = SI[6]; SI[6] = SI[7]; SI[7] = t;  \
        t = SR[1]; SR[1] = SR[5]; SR[5] = t;  t = SI[1]; SI[1] = SI[5]; SI[5] = t;  \
        t = SR[3]; SR[3] = SR[7]; SR[7] = t;  t = SI[3]; SI[3] = SI[7]; SI[7] = t;  \
    }

    // Layer 0: all 6 gates act on |000> before any entangler -> state is the
    // Kronecker product of the fused-gate first columns (a_q, conj(t_q)).
    #define LAYER0(WIN, SR, SI)                                                 \
    {                                                                           \
        float sn, cs;                                                           \
        __sincosf((WIN)[0] * pmc[0], &sn, &cs);                                 \
        float4 u = gcc[0];                                                      \
        float a0r = u.x * cs + u.z * sn,  a0i = u.y * cs + u.w * sn;            \
        float b0r = u.x * sn - u.z * cs,  b0i = u.w * cs - u.y * sn;            \
        __sincosf((WIN)[1] * pmc[1], &sn, &cs);                                 \
        u = gcc[1];                                                             \
        float a1r = u.x * cs + u.z * sn,  a1i = u.y * cs + u.w * sn;            \
        float b1r = u.x * sn - u.z * cs,  b1i = u.w * cs - u.y * sn;            \
        __sincosf((WIN)[2] * pmc[2], &sn, &cs);                                 \
        u = gcc[2];                                                             \
        float a2r = u.x * cs + u.z * sn,  a2i = u.y * cs + u.w * sn;            \
        float b2r = u.x * sn - u.z * cs,  b2i = u.w * cs - u.y * sn;            \
        float m0r = a1r * a2r - a1i * a2i,  m0i = a1r * a2i + a1i * a2r;        \
        float m1r = a1r * b2r - a1i * b2i,  m1i = a1r * b2i + a1i * b2r;        \
        float m2r = b1r * a2r - b1i * a2i,  m2i = b1r * a2i + b1i * a2r;        \
        float m3r = b1r * b2r - b1i * b2i,  m3i = b1r * b2i + b1i * b2r;        \
        SR[0] = a0r * m0r - a0i * m0i;  SI[0] = a0r * m0i + a0i * m0r;          \
        SR[1] = a0r * m1r - a0i * m1i;  SI[1] = a0r * m1i + a0i * m1r;          \
        SR[2] = a0r * m2r - a0i * m2i;  SI[2] = a0r * m2i + a0i * m2r;          \
        SR[3] = a0r * m3r - a0i * m3i;  SI[3] = a0r * m3i + a0i * m3r;          \
        SR[4] = b0r * m0r - b0i * m0i;  SI[4] = b0r * m0i + b0i * m0r;          \
        SR[5] = b0r * m1r - b0i * m1i;  SI[5] = b0r * m1i + b0i * m1r;          \
        SR[6] = b0r * m2r - b0i * m2i;  SI[6] = b0r * m2i + b0i * m2r;          \
        SR[7] = b0r * m3r - b0i * m3i;  SI[7] = b0r * m3i + b0i * m3r;          \
    }

    // Final wire-2 gate + CNOT ring + <Z2> folded: Ring' Z2 Ring = Z0 Z1 Z2,
    // M = V2' Z V2 = [[m,p],[conj(p),-m]]; <x|M|x> = m(|x0|^2-|x1|^2)+2Re(p x0* x1).
    #define MEASURE_FOLD(U, SN, CS, SR, SI, ACC)                                \
    {                                                                           \
        float ar = (U).x * (CS) + (U).z * (SN);                                 \
        float ai = (U).y * (CS) + (U).w * (SN);                                 \
        float tr = (U).x * (SN) - (U).z * (CS);                                 \
        float ti = (U).y * (SN) - (U).w * (CS);                                 \
        float m  = ar * ar + ai * ai - tr * tr - ti * ti;                       \
        float pr = -4.0f * (ar * tr + ai * ti);                                 \
        float pi = -4.0f * (ar * ti - ai * tr);                                 \
        float e0 = m  * (SR[0]*SR[0] + SI[0]*SI[0] - SR[1]*SR[1] - SI[1]*SI[1]) \
                 + pr * (SR[0]*SR[1] + SI[0]*SI[1])                             \
                 - pi * (SR[0]*SI[1] - SI[0]*SR[1]);                            \
        float e1 = m  * (SR[2]*SR[2] + SI[2]*SI[2] - SR[3]*SR[3] - SI[3]*SI[3]) \
                 + pr * (SR[2]*SR[3] + SI[2]*SI[3])                             \
                 - pi * (SR[2]*SI[3] - SI[2]*SR[3]);                            \
        float e2 = m  * (SR[4]*SR[4] + SI[4]*SI[4] - SR[5]*SR[5] - SI[5]*SI[5]) \
                 + pr * (SR[4]*SR[5] + SI[4]*SI[5])                             \
                 - pi * (SR[4]*SI[5] - SI[4]*SR[5]);                            \
        float e3 = m  * (SR[6]*SR[6] + SI[6]*SI[6] - SR[7]*SR[7] - SI[7]*SI[7]) \
                 + pr * (SR[6]*SR[7] + SI[6]*SI[7])                             \
                 - pi * (SR[6]*SI[7] - SI[6]*SR[7]);                            \
        ACC = e0 - e1 - e2 + e3;  /* Z0 Z1 parity signs */                      \
    }

    // Circuit A: positions k in [0, 225); circuit B: k + 225.
    int il0 = 0,              j0 = grp;                 // grp < 30
    int il1 = (grp + HALF) / ITDIM;
    int j1  = (grp + HALF) % ITDIM;

    #pragma unroll 1
    for (int k = grp; k < HALF; k += NGRP) {
        const float* win0 = chan + il0 * ROW_STRIDE + j0;
        const float* win1 = chan + il1 * ROW_STRIDE + j1;

        float sr0[8], si0[8], sr1[8], si1[8];

        LAYER0(win0, sr0, si0)
        LAYER0(win1, sr1, si1)
        CNOT_RING(sr0, si0)
        CNOT_RING(sr1, si1)

        // Layer 1: gate constants loaded once, applied to both circuits
        {
            float4 u = gcc[3]; float pm = pmc[3]; float sn, cs;
            __sincosf(win0[ROW_STRIDE + 0] * pm, &sn, &cs); APPLY_FUSED(u, sn, cs, sr0, si0, 4)
            __sincosf(win1[ROW_STRIDE + 0] * pm, &sn, &cs); APPLY_FUSED(u, sn, cs, sr1, si1, 4)
        }
        {
            float4 u = gcc[4]; float pm = pmc[4]; float sn, cs;
            __sincosf(win0[ROW_STRIDE + 1] * pm, &sn, &cs); APPLY_FUSED(u, sn, cs, sr0, si0, 2)
            __sincosf(win1[ROW_STRIDE + 1] * pm, &sn, &cs); APPLY_FUSED(u, sn, cs, sr1, si1, 2)
        }
        {
            float4 u = gcc[5]; float pm = pmc[5]; float sn, cs;
            __sincosf(win0[ROW_STRIDE + 2] * pm, &sn, &cs); APPLY_FUSED(u, sn, cs, sr0, si0, 1)
            __sincosf(win1[ROW_STRIDE + 2] * pm, &sn, &cs); APPLY_FUSED(u, sn, cs, sr1, si1, 1)
        }
        CNOT_RING(sr0, si0)
        CNOT_RING(sr1, si1)

        // Layer 2: wires 0,1 applied; wire-2 gate + ring + <Z2> folded
        {
            float4 u = gcc[6]; float pm = pmc[6]; float sn, cs;
            __sincosf(win0[2 * ROW_STRIDE + 0] * pm, &sn, &cs); APPLY_FUSED(u, sn, cs, sr0, si0, 4)
            __sincosf(win1[2 * ROW_STRIDE + 0] * pm, &sn, &cs); APPLY_FUSED(u, sn, cs, sr1, si1, 4)
        }
        {
            float4 u = gcc[7]; float pm = pmc[7]; float sn, cs;
            __sincosf(win0[2 * ROW_STRIDE + 1] * pm, &sn, &cs); APPLY_FUSED(u, sn, cs, sr0, si0, 2)
            __sincosf(win1[2 * ROW_STRIDE + 1] * pm, &sn, &cs); APPLY_FUSED(u, sn, cs, sr1, si1, 2)
        }

        float acc0, acc1;
        {
            float4 u = gcc[8]; float pm = pmc[8]; float sn, cs;
            __sincosf(win0[2 * ROW_STRIDE + 2] * pm, &sn, &cs);
            MEASURE_FOLD(u, sn, cs, sr0, si0, acc0)
            __sincosf(win1[2 * ROW_STRIDE + 2] * pm, &sn, &cs);
            MEASURE_FOLD(u, sn, cs, sr1, si1, acc1)
        }

        // reduce both circuits over the 8 cin lanes
        acc0 += __shfl_xor_sync(0xFFFFFFFFu, acc0, 1);
        acc1 += __shfl_xor_sync(0xFFFFFFFFu, acc1, 1);
        acc0 += __shfl_xor_sync(0xFFFFFFFFu, acc0, 2);
        acc1 += __shfl_xor_sync(0xFFFFFFFFu, acc1, 2);
        acc0 += __shfl_xor_sync(0xFFFFFFFFu, acc0, 4);
        acc1 += __shfl_xor_sync(0xFFFFFFFFu, acc1, 4);
        if (cin == 0) {
            outp[il0 * ITDIM + j0] = acc0;
            outp[il1 * ITDIM + j1] = acc1;
        }

        // incremental index update (no div/mod), step 16 < 30 -> single wrap
        j0 += NGRP; if (j0 >= ITDIM) { j0 -= ITDIM; il0++; }
        j1 += NGRP; if (j1 >= ITDIM) { j1 -= ITDIM; il1++; }
    }

    #undef APPLY_FUSED
    #undef CNOT_RING
    #undef LAYER0
    #undef MEASURE_FOLD
}

extern "C" void kernel_launch(void* const* d_in, const int* in_sizes, int n_in,
                              void* d_out, int out_size)
{
    const float* inputs       = (const float*)d_in[0];
    const float* input_params = (const float*)d_in[1];
    const float* weights      = (const float*)d_in[2];
    float* out = (float*)d_out;

    precompute_kernel<<<(NGATE + 127) / 128, 128>>>(input_params, weights);
    dim3 grid(COUT, BB, NBAND);   // 16 x 32 x 2 = 1024 blocks
    qconv_kernel<<<grid, NTHREADS>>>(inputs, out);
}